// round 7
// baseline (speedup 1.0000x reference)
#include <cuda_runtime.h>
#include <cstdint>
#include <cstddef>
#include <math.h>

#define LABEL_DIM 173
#define VECT_DIM  32
#define NBLOCKS   1184
#define NTHREADS  256
#define PROW      36          // padded partial row: 32 colsums + 1 sumsq + pad

// Per-block partials + completion counter. Partials fully overwritten each
// launch; the counter returns to 0 at the end of every launch (last block
// resets it) -> graph-replay deterministic.
__device__ float    g_partial[NBLOCKS * PROW];
__device__ unsigned g_count = 0;

// ---------------------------------------------------------------------------
// Fused kernel: streaming column-sum + sumsq reduce over x (float4 view);
// the LAST block to finish combines the L2-hot partials and computes the
// 173 cosine distances + argmin.
//
// Lane->column mapping: grid*block and the grid stride are multiples of 8,
// so a thread's float4 index i always satisfies i % 8 == threadIdx.x % 8:
// lane l owns columns 4*(l%8) .. 4*(l%8)+3.
// ---------------------------------------------------------------------------
__global__ void __launch_bounds__(NTHREADS)
vd_fused_kernel(const float4* __restrict__ x, long long n4,
                const float* __restrict__ means,
                float* __restrict__ out) {
    const unsigned lane = threadIdx.x & 31u;
    const unsigned wid  = threadIdx.x >> 5;

    // ---- Phase 1: streaming reduce (proven round-5 loop shape) ----
    float4 acc = make_float4(0.f, 0.f, 0.f, 0.f);
    float  sq  = 0.f;

    long long stride = (long long)gridDim.x * blockDim.x;
    for (long long i = (long long)blockIdx.x * blockDim.x + threadIdx.x;
         i < n4; i += stride) {
        float4 v = x[i];
        acc.x += v.x; acc.y += v.y; acc.z += v.z; acc.w += v.w;
        sq += v.x * v.x + v.y * v.y + v.z * v.z + v.w * v.w;
    }

    // sumsq: full warp tree
    #pragma unroll
    for (int off = 16; off >= 1; off >>= 1)
        sq += __shfl_xor_sync(0xFFFFFFFFu, sq, off);

    // column sums: lanes l, l^8, l^16, l^24 own the same 4-column group.
    #pragma unroll
    for (int off = 16; off >= 8; off >>= 1) {
        acc.x += __shfl_xor_sync(0xFFFFFFFFu, acc.x, off);
        acc.y += __shfl_xor_sync(0xFFFFFFFFu, acc.y, off);
        acc.z += __shfl_xor_sync(0xFFFFFFFFu, acc.z, off);
        acc.w += __shfl_xor_sync(0xFFFFFFFFu, acc.w, off);
    }

    __shared__ float s_warp[NTHREADS / 32][PROW];
    if (lane < 8) {
        s_warp[wid][lane * 4 + 0] = acc.x;
        s_warp[wid][lane * 4 + 1] = acc.y;
        s_warp[wid][lane * 4 + 2] = acc.z;
        s_warp[wid][lane * 4 + 3] = acc.w;
    }
    if (lane == 0) s_warp[wid][32] = sq;
    __syncthreads();

    if (threadIdx.x < 33) {
        float v = 0.f;
        #pragma unroll
        for (int w = 0; w < NTHREADS / 32; w++) v += s_warp[w][threadIdx.x];
        g_partial[blockIdx.x * PROW + threadIdx.x] = v;
    }

    // ---- Last-block election ----
    __shared__ bool s_last;
    __threadfence();                     // partials visible before counter bump
    if (threadIdx.x == 0) {
        unsigned prev = atomicAdd(&g_count, 1u);
        s_last = (prev == NBLOCKS - 1);
    }
    __syncthreads();
    if (!s_last) return;

    // ---- Phase 2 (last block only): combine L2-hot partials, distances, argmin ----
    if (threadIdx.x == 0) g_count = 0;   // reset for next graph replay

    __shared__ float s_part[8][VECT_DIM];
    __shared__ float s_xsum[VECT_DIM];
    __shared__ float s_sumsq;
    __shared__ float s_dist[NTHREADS];
    __shared__ int   s_idx[NTHREADS];

    int t = threadIdx.x;
    int r = t >> 5;                      // 0..7
    int c = t & 31;                      // 0..31

    {
        float a = 0.f;
        for (int b = r; b < NBLOCKS; b += 8)
            a += g_partial[b * PROW + c];
        s_part[r][c] = a;
    }
    // sumsq combine: 32 threads, then warp tree
    if (t < 32) {
        float sqp = 0.f;
        for (int b = t; b < NBLOCKS; b += 32)
            sqp += g_partial[b * PROW + 32];
        #pragma unroll
        for (int off = 16; off >= 1; off >>= 1)
            sqp += __shfl_xor_sync(0xFFFFFFFFu, sqp, off);
        if (t == 0) s_sumsq = sqp;
    }
    __syncthreads();

    if (t < VECT_DIM) {
        float v = 0.f;
        #pragma unroll
        for (int w = 0; w < 8; w++) v += s_part[w][t];
        s_xsum[t] = v;
    }
    __syncthreads();

    float xnorm = sqrtf(s_sumsq);

    float dist = INFINITY;
    if (t < LABEL_DIM) {
        const float* m = means + (size_t)t * VECT_DIM;
        float dot = 0.f, ysq = 0.f;
        #pragma unroll
        for (int d = 0; d < VECT_DIM; d++) {
            float mv = m[d];
            dot += s_xsum[d] * mv;
            ysq += mv * mv;
        }
        dist = 1.0f - dot / (xnorm * sqrtf(ysq));
    }
    s_dist[t] = (t < LABEL_DIM) ? dist : INFINITY;
    s_idx[t]  = (t < LABEL_DIM) ? t : 0;
    __syncthreads();

    for (int s = NTHREADS / 2; s >= 1; s >>= 1) {
        if (t < s) {
            float a = s_dist[t], b = s_dist[t + s];
            bool take = (b < a) || (isnan(a) && !isnan(b));
            if (take) { s_dist[t] = b; s_idx[t] = s_idx[t + s]; }
        }
        __syncthreads();
    }
    if (t == 0) out[0] = (float)s_idx[0];   // __output__ dtype is float32
}

// ---------------------------------------------------------------------------
// Scalar fallback path (unaligned x — never expected with cudaMalloc bufs).
// ---------------------------------------------------------------------------
__global__ void vd_reduce_scalar(const float* __restrict__ x, long long n) {
    const unsigned lane = threadIdx.x & 31u;
    const unsigned wid  = threadIdx.x >> 5;

    float acc = 0.f, sq = 0.f;
    long long stride = (long long)gridDim.x * blockDim.x;
    for (long long i = (long long)blockIdx.x * blockDim.x + threadIdx.x;
         i < n; i += stride) {
        float v = x[i];
        acc += v; sq += v * v;
    }
    #pragma unroll
    for (int off = 16; off >= 1; off >>= 1)
        sq += __shfl_xor_sync(0xFFFFFFFFu, sq, off);

    __shared__ float s_warp[NTHREADS / 32][PROW];
    s_warp[wid][lane] = acc;           // lane l owns column l (stride % 32 == 0)
    if (lane == 0) s_warp[wid][32] = sq;
    __syncthreads();

    if (threadIdx.x < 33) {
        float v = 0.f;
        #pragma unroll
        for (int w = 0; w < NTHREADS / 32; w++) v += s_warp[w][threadIdx.x];
        g_partial[blockIdx.x * PROW + threadIdx.x] = v;
    }
}

__global__ void vd_finalize_kernel(const float* __restrict__ means,
                                   float* __restrict__ out) {
    __shared__ float s_part[8][VECT_DIM];
    __shared__ float s_xsum[VECT_DIM];
    __shared__ float s_sumsq;
    __shared__ float s_dist[NTHREADS];
    __shared__ int   s_idx[NTHREADS];

    int t = threadIdx.x;
    int r = t >> 5, c = t & 31;
    {
        float a = 0.f;
        for (int b = r; b < NBLOCKS; b += 8)
            a += g_partial[b * PROW + c];
        s_part[r][c] = a;
    }
    if (t < 32) {
        float sqp = 0.f;
        for (int b = t; b < NBLOCKS; b += 32)
            sqp += g_partial[b * PROW + 32];
        #pragma unroll
        for (int off = 16; off >= 1; off >>= 1)
            sqp += __shfl_xor_sync(0xFFFFFFFFu, sqp, off);
        if (t == 0) s_sumsq = sqp;
    }
    __syncthreads();
    if (t < VECT_DIM) {
        float v = 0.f;
        #pragma unroll
        for (int w = 0; w < 8; w++) v += s_part[w][t];
        s_xsum[t] = v;
    }
    __syncthreads();

    float xnorm = sqrtf(s_sumsq);
    float dist = INFINITY;
    if (t < LABEL_DIM) {
        const float* m = means + (size_t)t * VECT_DIM;
        float dot = 0.f, ysq = 0.f;
        #pragma unroll
        for (int d = 0; d < VECT_DIM; d++) {
            float mv = m[d];
            dot += s_xsum[d] * mv; ysq += mv * mv;
        }
        dist = 1.0f - dot / (xnorm * sqrtf(ysq));
    }
    s_dist[t] = (t < LABEL_DIM) ? dist : INFINITY;
    s_idx[t]  = (t < LABEL_DIM) ? t : 0;
    __syncthreads();
    for (int s = NTHREADS / 2; s >= 1; s >>= 1) {
        if (t < s) {
            float a = s_dist[t], b = s_dist[t + s];
            bool take = (b < a) || (isnan(a) && !isnan(b));
            if (take) { s_dist[t] = b; s_idx[t] = s_idx[t + s]; }
        }
        __syncthreads();
    }
    if (t == 0) out[0] = (float)s_idx[0];
}

// ---------------------------------------------------------------------------
extern "C" void kernel_launch(void* const* d_in, const int* in_sizes, int n_in,
                              void* d_out, int out_size) {
    // x = largest input; means = the input with exactly 173*32 elements.
    int xi = 0;
    for (int i = 1; i < n_in; i++)
        if (in_sizes[i] > in_sizes[xi]) xi = i;
    int mi = -1;
    for (int i = 0; i < n_in; i++)
        if (i != xi && in_sizes[i] == LABEL_DIM * VECT_DIM) { mi = i; break; }
    if (mi < 0) { mi = (xi == 0 && n_in > 1) ? 1 : 0; }

    const float* x     = (const float*)d_in[xi];
    const float* means = (const float*)d_in[mi];
    long long n = (long long)in_sizes[xi];

    bool aligned16 = ((((unsigned long long)(size_t)x) & 15ull) == 0) &&
                     (n % 4 == 0);
    if (aligned16) {
        vd_fused_kernel<<<NBLOCKS, NTHREADS>>>((const float4*)x, n / 4,
                                               means, (float*)d_out);
    } else {
        vd_reduce_scalar<<<NBLOCKS, NTHREADS>>>(x, n);
        vd_finalize_kernel<<<1, NTHREADS>>>(means, (float*)d_out);
    }
}

// round 8
// speedup vs baseline: 1.1474x; 1.1474x over previous
#include <cuda_runtime.h>
#include <cstdint>
#include <cstddef>
#include <math.h>

#define LABEL_DIM 173
#define VECT_DIM  32
#define NBLOCKS   1184
#define NTHREADS  256
#define PROW      36          // padded partial row: 32 colsums + 1 sumsq + pad

// Per-block partials + completion counter. Partials fully overwritten each
// launch; the counter returns to 0 at the end of every launch (last block
// resets it) -> graph-replay deterministic.
__device__ float    g_partial[NBLOCKS * PROW];
__device__ unsigned g_count = 0;

// ---------------------------------------------------------------------------
// Fused kernel. __launch_bounds__(256, 8) caps regs at 32 so 8 CTAs/SM are
// resident (64 warps) — the hot streaming loop needs ~40+ outstanding
// warp-loads per SM to hide DRAM latency. Phase-2 spills (if any) execute in
// exactly one block, cost-free.
//
// Lane->column mapping: grid*block and the grid stride are multiples of 8,
// so a thread's float4 index i always satisfies i % 8 == threadIdx.x % 8:
// lane l owns columns 4*(l%8) .. 4*(l%8)+3.
// ---------------------------------------------------------------------------
__global__ void __launch_bounds__(NTHREADS, 8)
vd_fused_kernel(const float4* __restrict__ x, long long n4,
                const float* __restrict__ means,
                float* __restrict__ out) {
    const unsigned lane = threadIdx.x & 31u;
    const unsigned wid  = threadIdx.x >> 5;

    // ---- Phase 1: streaming reduce ----
    float4 acc = make_float4(0.f, 0.f, 0.f, 0.f);
    float  sq  = 0.f;

    long long stride = (long long)gridDim.x * blockDim.x;
    for (long long i = (long long)blockIdx.x * blockDim.x + threadIdx.x;
         i < n4; i += stride) {
        float4 v = __ldcs(&x[i]);        // streaming: touched once, evict-first
        acc.x += v.x; acc.y += v.y; acc.z += v.z; acc.w += v.w;
        sq += v.x * v.x + v.y * v.y + v.z * v.z + v.w * v.w;
    }

    // sumsq: full warp tree
    #pragma unroll
    for (int off = 16; off >= 1; off >>= 1)
        sq += __shfl_xor_sync(0xFFFFFFFFu, sq, off);

    // column sums: lanes l, l^8, l^16, l^24 own the same 4-column group.
    #pragma unroll
    for (int off = 16; off >= 8; off >>= 1) {
        acc.x += __shfl_xor_sync(0xFFFFFFFFu, acc.x, off);
        acc.y += __shfl_xor_sync(0xFFFFFFFFu, acc.y, off);
        acc.z += __shfl_xor_sync(0xFFFFFFFFu, acc.z, off);
        acc.w += __shfl_xor_sync(0xFFFFFFFFu, acc.w, off);
    }

    __shared__ float s_warp[NTHREADS / 32][PROW];
    if (lane < 8) {
        s_warp[wid][lane * 4 + 0] = acc.x;
        s_warp[wid][lane * 4 + 1] = acc.y;
        s_warp[wid][lane * 4 + 2] = acc.z;
        s_warp[wid][lane * 4 + 3] = acc.w;
    }
    if (lane == 0) s_warp[wid][32] = sq;
    __syncthreads();

    if (threadIdx.x < 33) {
        float v = 0.f;
        #pragma unroll
        for (int w = 0; w < NTHREADS / 32; w++) v += s_warp[w][threadIdx.x];
        g_partial[blockIdx.x * PROW + threadIdx.x] = v;
    }

    // ---- Last-block election ----
    __shared__ bool s_last;
    __threadfence();                     // partials visible before counter bump
    if (threadIdx.x == 0) {
        unsigned prev = atomicAdd(&g_count, 1u);
        s_last = (prev == NBLOCKS - 1);
    }
    __syncthreads();
    if (!s_last) return;

    // ---- Phase 2 (last block only): combine L2-hot partials, distances, argmin ----
    if (threadIdx.x == 0) g_count = 0;   // reset for next graph replay

    __shared__ float s_part[8][VECT_DIM];
    __shared__ float s_xsum[VECT_DIM];
    __shared__ float s_sumsq;
    __shared__ float s_dist[NTHREADS];
    __shared__ int   s_idx[NTHREADS];

    int t = threadIdx.x;
    int r = t >> 5;                      // 0..7
    int c = t & 31;                      // 0..31

    {
        float a = 0.f;
        for (int b = r; b < NBLOCKS; b += 8)
            a += g_partial[b * PROW + c];
        s_part[r][c] = a;
    }
    if (t < 32) {
        float sqp = 0.f;
        for (int b = t; b < NBLOCKS; b += 32)
            sqp += g_partial[b * PROW + 32];
        #pragma unroll
        for (int off = 16; off >= 1; off >>= 1)
            sqp += __shfl_xor_sync(0xFFFFFFFFu, sqp, off);
        if (t == 0) s_sumsq = sqp;
    }
    __syncthreads();

    if (t < VECT_DIM) {
        float v = 0.f;
        #pragma unroll
        for (int w = 0; w < 8; w++) v += s_part[w][t];
        s_xsum[t] = v;
    }
    __syncthreads();

    float xnorm = sqrtf(s_sumsq);

    float dist = INFINITY;
    if (t < LABEL_DIM) {
        const float* m = means + (size_t)t * VECT_DIM;
        float dot = 0.f, ysq = 0.f;
        #pragma unroll
        for (int d = 0; d < VECT_DIM; d++) {
            float mv = m[d];
            dot += s_xsum[d] * mv;
            ysq += mv * mv;
        }
        dist = 1.0f - dot / (xnorm * sqrtf(ysq));
    }
    s_dist[t] = (t < LABEL_DIM) ? dist : INFINITY;
    s_idx[t]  = (t < LABEL_DIM) ? t : 0;
    __syncthreads();

    for (int s = NTHREADS / 2; s >= 1; s >>= 1) {
        if (t < s) {
            float a = s_dist[t], b = s_dist[t + s];
            bool take = (b < a) || (isnan(a) && !isnan(b));
            if (take) { s_dist[t] = b; s_idx[t] = s_idx[t + s]; }
        }
        __syncthreads();
    }
    if (t == 0) out[0] = (float)s_idx[0];   // __output__ dtype is float32
}

// ---------------------------------------------------------------------------
// Scalar fallback path (unaligned x — never expected with cudaMalloc bufs).
// ---------------------------------------------------------------------------
__global__ void vd_reduce_scalar(const float* __restrict__ x, long long n) {
    const unsigned lane = threadIdx.x & 31u;
    const unsigned wid  = threadIdx.x >> 5;

    float acc = 0.f, sq = 0.f;
    long long stride = (long long)gridDim.x * blockDim.x;
    for (long long i = (long long)blockIdx.x * blockDim.x + threadIdx.x;
         i < n; i += stride) {
        float v = x[i];
        acc += v; sq += v * v;
    }
    #pragma unroll
    for (int off = 16; off >= 1; off >>= 1)
        sq += __shfl_xor_sync(0xFFFFFFFFu, sq, off);

    __shared__ float s_warp[NTHREADS / 32][PROW];
    s_warp[wid][lane] = acc;           // lane l owns column l (stride % 32 == 0)
    if (lane == 0) s_warp[wid][32] = sq;
    __syncthreads();

    if (threadIdx.x < 33) {
        float v = 0.f;
        #pragma unroll
        for (int w = 0; w < NTHREADS / 32; w++) v += s_warp[w][threadIdx.x];
        g_partial[blockIdx.x * PROW + threadIdx.x] = v;
    }
}

__global__ void vd_finalize_kernel(const float* __restrict__ means,
                                   float* __restrict__ out) {
    __shared__ float s_part[8][VECT_DIM];
    __shared__ float s_xsum[VECT_DIM];
    __shared__ float s_sumsq;
    __shared__ float s_dist[NTHREADS];
    __shared__ int   s_idx[NTHREADS];

    int t = threadIdx.x;
    int r = t >> 5, c = t & 31;
    {
        float a = 0.f;
        for (int b = r; b < NBLOCKS; b += 8)
            a += g_partial[b * PROW + c];
        s_part[r][c] = a;
    }
    if (t < 32) {
        float sqp = 0.f;
        for (int b = t; b < NBLOCKS; b += 32)
            sqp += g_partial[b * PROW + 32];
        #pragma unroll
        for (int off = 16; off >= 1; off >>= 1)
            sqp += __shfl_xor_sync(0xFFFFFFFFu, sqp, off);
        if (t == 0) s_sumsq = sqp;
    }
    __syncthreads();
    if (t < VECT_DIM) {
        float v = 0.f;
        #pragma unroll
        for (int w = 0; w < 8; w++) v += s_part[w][t];
        s_xsum[t] = v;
    }
    __syncthreads();

    float xnorm = sqrtf(s_sumsq);
    float dist = INFINITY;
    if (t < LABEL_DIM) {
        const float* m = means + (size_t)t * VECT_DIM;
        float dot = 0.f, ysq = 0.f;
        #pragma unroll
        for (int d = 0; d < VECT_DIM; d++) {
            float mv = m[d];
            dot += s_xsum[d] * mv; ysq += mv * mv;
        }
        dist = 1.0f - dot / (xnorm * sqrtf(ysq));
    }
    s_dist[t] = (t < LABEL_DIM) ? dist : INFINITY;
    s_idx[t]  = (t < LABEL_DIM) ? t : 0;
    __syncthreads();
    for (int s = NTHREADS / 2; s >= 1; s >>= 1) {
        if (t < s) {
            float a = s_dist[t], b = s_dist[t + s];
            bool take = (b < a) || (isnan(a) && !isnan(b));
            if (take) { s_dist[t] = b; s_idx[t] = s_idx[t + s]; }
        }
        __syncthreads();
    }
    if (t == 0) out[0] = (float)s_idx[0];
}

// ---------------------------------------------------------------------------
extern "C" void kernel_launch(void* const* d_in, const int* in_sizes, int n_in,
                              void* d_out, int out_size) {
    // x = largest input; means = the input with exactly 173*32 elements.
    int xi = 0;
    for (int i = 1; i < n_in; i++)
        if (in_sizes[i] > in_sizes[xi]) xi = i;
    int mi = -1;
    for (int i = 0; i < n_in; i++)
        if (i != xi && in_sizes[i] == LABEL_DIM * VECT_DIM) { mi = i; break; }
    if (mi < 0) { mi = (xi == 0 && n_in > 1) ? 1 : 0; }

    const float* x     = (const float*)d_in[xi];
    const float* means = (const float*)d_in[mi];
    long long n = (long long)in_sizes[xi];

    bool aligned16 = ((((unsigned long long)(size_t)x) & 15ull) == 0) &&
                     (n % 4 == 0);
    if (aligned16) {
        vd_fused_kernel<<<NBLOCKS, NTHREADS>>>((const float4*)x, n / 4,
                                               means, (float*)d_out);
    } else {
        vd_reduce_scalar<<<NBLOCKS, NTHREADS>>>(x, n);
        vd_finalize_kernel<<<1, NTHREADS>>>(means, (float*)d_out);
    }
}